// round 17
// baseline (speedup 1.0000x reference)
#include <cuda_runtime.h>
#include <cuda_bf16.h>
#include <cuda_fp16.h>
#include <cstdint>
#include <math.h>

// ---------------- problem constants ----------------
#define BB     4
#define SS     4096
#define HIDD   1024
#define NHH    16
#define DD     64
#define WINN   512
#define CHUNKK 128
#define NWW    8
#define NCC    32
#define SCALEF 0.125f
#define MTOK   (BB*SS)   // 16384
#define GK     1024

// ---------------- scratch (device globals) ----------------
__device__ __half g_q16[MTOK*HIDD];
__device__ __half g_k16[MTOK*HIDD];
__device__ __half g_v16[MTOK*HIDD];
__device__ __half g_rfak16[BB*NHH*NCC*DD];
__device__ __half g_rfav16[BB*NHH*NCC*DD];
__device__ __half g_hid_h[MTOK*HIDD];
__device__ __half g_ao_h[MTOK*HIDD];
__device__ __half g_w16[4*HIDD*HIDD];

// ================= helpers =================
__device__ __forceinline__ uint32_t smem_u32(const void* p) {
    uint32_t a;
    asm("{ .reg .u64 t; cvta.to.shared.u64 t, %1; cvt.u32.u64 %0, t; }" : "=r"(a) : "l"(p));
    return a;
}

#define LDSM_X4(r, a)                                                          \
    asm volatile("ldmatrix.sync.aligned.m8n8.x4.shared.b16 {%0,%1,%2,%3}, [%4];" \
        : "=r"((r)[0]), "=r"((r)[1]), "=r"((r)[2]), "=r"((r)[3]) : "r"(a))

#define LDSM_X4T(r, a)                                                         \
    asm volatile("ldmatrix.sync.aligned.m8n8.x4.trans.shared.b16 {%0,%1,%2,%3}, [%4];" \
        : "=r"((r)[0]), "=r"((r)[1]), "=r"((r)[2]), "=r"((r)[3]) : "r"(a))

#define MMAH16816(c, a, b0, b1)                                                \
    asm volatile("mma.sync.aligned.m16n8k16.row.col.f32.f16.f16.f32 "          \
        "{%0,%1,%2,%3}, {%4,%5,%6,%7}, {%8,%9}, {%0,%1,%2,%3};"                \
        : "+f"((c)[0]), "+f"((c)[1]), "+f"((c)[2]), "+f"((c)[3])               \
        : "r"((a)[0]), "r"((a)[1]), "r"((a)[2]), "r"((a)[3]), "r"(b0), "r"(b1))

#define MMAH16816R(c, a0, a1, a2, a3, b0, b1)                                  \
    asm volatile("mma.sync.aligned.m16n8k16.row.col.f32.f16.f16.f32 "          \
        "{%0,%1,%2,%3}, {%4,%5,%6,%7}, {%8,%9}, {%0,%1,%2,%3};"                \
        : "+f"((c)[0]), "+f"((c)[1]), "+f"((c)[2]), "+f"((c)[3])               \
        : "r"(a0), "r"(a1), "r"(a2), "r"(a3), "r"(b0), "r"(b1))

#define CPASYNC16(dst, src) \
    asm volatile("cp.async.cg.shared.global [%0], [%1], 16;" :: "r"(dst), "l"(src) : "memory")
#define CPASYNC16P(dst, src, sz) \
    asm volatile("cp.async.cg.shared.global [%0], [%1], 16, %2;" :: "r"(dst), "l"(src), "r"(sz) : "memory")
#define CPCOMMIT() asm volatile("cp.async.commit_group;" ::: "memory")
#define CPWAIT1()  asm volatile("cp.async.wait_group 1;" ::: "memory")
#define CPWAIT0()  asm volatile("cp.async.wait_group 0;" ::: "memory")

__device__ __forceinline__ uint32_t packh2(float x, float y) {
    __half2 h;
    h.x = __float2half(x); h.y = __float2half(y);
    return *(uint32_t*)&h;
}

// ================= convert kernels =================
__global__ void cvt16_one(const float* __restrict__ src, __half* __restrict__ dst, int n4) {
    int i = blockIdx.x * blockDim.x + threadIdx.x;
    if (i >= n4) return;
    float4 f = ((const float4*)src)[i];
    ((uint2*)dst)[i] = make_uint2(packh2(f.x, f.y), packh2(f.z, f.w));
}

__global__ void cvt16_all(const float* __restrict__ W0, const float* __restrict__ W1,
                          const float* __restrict__ W2, const float* __restrict__ W3,
                          __half* __restrict__ dst, int n4) {
    int i = blockIdx.x * blockDim.x + threadIdx.x;
    if (i >= n4) return;
    const float* src = (blockIdx.y == 0) ? W0 : (blockIdx.y == 1) ? W1 : (blockIdx.y == 2) ? W2 : W3;
    float4 f = ((const float4*)src)[i];
    ((uint2*)(dst + (size_t)blockIdx.y * HIDD * HIDD))[i] = make_uint2(packh2(f.x, f.y), packh2(f.z, f.w));
}

// ============ fp16 GEMM: C = A[M,K] * B16[N,K]^T, fused RoPE, fp16 or fp32 out ============
// CTA 128x256, 512 threads, warp tile 32x64, K-chunk 64, 3-stage cp.async
#define QSTAGE 3
#define ATILE  18432
#define BTILE  36864
#define QBUF   (ATILE + BTILE)          // 55296
#define QSMEM  (QSTAGE * QBUF)          // 165888

__global__ void __launch_bounds__(512, 1)
gemm_f16(const __half* __restrict__ Ah,
         const __half* __restrict__ Bw,
         __half* __restrict__ H0, __half* __restrict__ H1, __half* __restrict__ H2,
         float* __restrict__ Cf,
         const float* __restrict__ cosT, const float* __restrict__ sinT,
         int dorope, int out16) {
    extern __shared__ char dsm[];
    const uint32_t sbase = smem_u32(dsm);

    const int tid  = threadIdx.x;
    const int lane = tid & 31;
    const int wid  = tid >> 5;       // 0..15
    const int wm   = wid & 3;        // 0..3 (32-row stripes)
    const int wn   = wid >> 2;       // 0..3 (64-col stripes)
    const int m0   = blockIdx.y * 128;
    const int n0   = blockIdx.x * 256;

    const int sel = n0 >> 10;
    const int nc0 = n0 & 1023;

    const int rowoff = ((lane >> 3) & 1) * 8 + (lane & 7);
    const int koff   = (lane >> 4) * 8;

    uint32_t aoffb[2], boffb[4];
#pragma unroll
    for (int mf = 0; mf < 2; mf++)
        aoffb[mf] = (uint32_t)(wm * 32 + mf * 16 + rowoff) * 144 + koff * 2;
#pragma unroll
    for (int nb = 0; nb < 4; nb++)
        boffb[nb] = ATILE + (uint32_t)(wn * 64 + nb * 16 + rowoff) * 144 + koff * 2;

    const int arow0 = tid >> 3, ac8 = tid & 7;
    float acc[2][8][4];
#pragma unroll
    for (int i = 0; i < 2; i++)
#pragma unroll
        for (int j = 0; j < 8; j++)
#pragma unroll
            for (int r = 0; r < 4; r++) acc[i][j][r] = 0.f;

    auto issue_stage = [&](int kc) {
        uint32_t base = sbase + (kc % QSTAGE) * QBUF;
        int kcol = kc * 64 + ac8 * 8;
#pragma unroll
        for (int i = 0; i < 2; i++) {
            int r = arow0 + i * 64;
            CPASYNC16(base + (uint32_t)r * 144 + ac8 * 16,
                      Ah + (size_t)(m0 + r) * GK + kcol);
        }
#pragma unroll
        for (int i = 0; i < 4; i++) {
            int r = arow0 + i * 64;
            CPASYNC16(base + ATILE + (uint32_t)r * 144 + ac8 * 16,
                      Bw + (size_t)(n0 + r) * GK + kcol);
        }
        CPCOMMIT();
    };

    issue_stage(0);
    issue_stage(1);

    for (int kc = 0; kc < GK / 64; kc++) {
        CPWAIT1();
        __syncthreads();
        if (kc + 2 < GK / 64) issue_stage(kc + 2);
        else CPCOMMIT();

        const uint32_t stb = sbase + (kc % QSTAGE) * QBUF;

#pragma unroll
        for (int ks = 0; ks < 4; ks++) {
            const uint32_t ksb = stb + ks * 32;
            uint32_t af[2][4], bf[4][4];
#pragma unroll
            for (int nb = 0; nb < 4; nb++)
                LDSM_X4(bf[nb], ksb + boffb[nb]);
#pragma unroll
            for (int mf = 0; mf < 2; mf++)
                LDSM_X4(af[mf], ksb + aoffb[mf]);
#pragma unroll
            for (int mf = 0; mf < 2; mf++)
#pragma unroll
                for (int nf = 0; nf < 8; nf++)
                    MMAH16816(acc[mf][nf], af[mf], bf[nf >> 1][nf & 1], bf[nf >> 1][(nf & 1) + 2]);
        }
    }

    // ---- fused RoPE (q,k only) ----
    if (dorope && sel < 2) {
        CPWAIT0();
        __syncthreads();
        float* csm = (float*)dsm;            // [128][64]
        float* ssm = csm + 8192;             // [128][64]
        const int s0 = m0 & (SS - 1);
        for (int i = tid; i < 2048; i += 512) {
            ((float4*)csm)[i] = ((const float4*)(cosT + (size_t)s0 * DD))[i];
            ((float4*)ssm)[i] = ((const float4*)(sinT + (size_t)s0 * DD))[i];
        }
        __syncthreads();
#pragma unroll
        for (int mf = 0; mf < 2; mf++) {
            int rl0 = wm * 32 + mf * 16 + (lane >> 2);
#pragma unroll
            for (int hf = 0; hf < 2; hf++) {
                int rl = rl0 + hf * 8;
#pragma unroll
                for (int nf = 0; nf < 4; nf++) {
#pragma unroll
                    for (int j = 0; j < 2; j++) {
                        int d0 = nf * 8 + (lane & 3) * 2 + j;
                        float c1 = csm[rl * 64 + d0],      s1 = ssm[rl * 64 + d0];
                        float c2 = csm[rl * 64 + d0 + 32], s2 = ssm[rl * 64 + d0 + 32];
                        float x1 = acc[mf][nf][hf * 2 + j];
                        float x2 = acc[mf][nf + 4][hf * 2 + j];
                        acc[mf][nf][hf * 2 + j]     = x1 * c1 - x2 * s1;
                        acc[mf][nf + 4][hf * 2 + j] = x2 * c2 + x1 * s2;
                    }
                }
            }
        }
    }

    if (out16) {
        __half* Ch = (sel == 0) ? H0 : (sel == 1) ? H1 : H2;
        const float sc = (sel == 0) ? SCALEF : 1.f;   // pre-scale q by SCALEF
#pragma unroll
        for (int mf = 0; mf < 2; mf++) {
            int r0 = m0 + wm * 32 + mf * 16 + (lane >> 2);
#pragma unroll
            for (int nf = 0; nf < 8; nf++) {
                int c0 = nc0 + wn * 64 + nf * 8 + (lane & 3) * 2;
                *(uint32_t*)(Ch + (size_t)r0 * HIDD + c0)       = packh2(acc[mf][nf][0] * sc, acc[mf][nf][1] * sc);
                *(uint32_t*)(Ch + (size_t)(r0 + 8) * HIDD + c0) = packh2(acc[mf][nf][2] * sc, acc[mf][nf][3] * sc);
            }
        }
    } else {
#pragma unroll
        for (int mf = 0; mf < 2; mf++) {
            int r0 = m0 + wm * 32 + mf * 16 + (lane >> 2);
#pragma unroll
            for (int nf = 0; nf < 8; nf++) {
                int c0 = nc0 + wn * 64 + nf * 8 + (lane & 3) * 2;
                *(float2*)(Cf + (size_t)r0 * HIDD + c0)       = make_float2(acc[mf][nf][0], acc[mf][nf][1]);
                *(float2*)(Cf + (size_t)(r0 + 8) * HIDD + c0) = make_float2(acc[mf][nf][2], acc[mf][nf][3]);
            }
        }
    }
}

// ================= per-chunk RFA summaries (fp16 in/out, fp32 math) =================
__global__ void __launch_bounds__(128) rfa_kernel(const __half* __restrict__ k,
                                                  const __half* __restrict__ v,
                                                  const float* __restrict__ mu,
                                                  const float* __restrict__ phi,
                                                  __half* __restrict__ rk,
                                                  __half* __restrict__ rv) {
    int bh = blockIdx.x / NCC;
    int c  = blockIdx.x % NCC;
    int b  = bh / NHH, h = bh % NHH;
    int j  = threadIdx.x;
    __shared__ float sb[CHUNKK], sg[CHUNKK];
    const __half* kbase = k + (((size_t)b * SS + c * CHUNKK) * NHH + h) * DD;
    const __half* vbase = v + (((size_t)b * SS + c * CHUNKK) * NHH + h) * DD;
    const __half* kr = kbase + (size_t)j * HIDD;
    float dm = 0.f, dp = 0.f, nn = 0.f;
#pragma unroll
    for (int d = 0; d < DD; d++) {
        float kv = __half2float(kr[d]);
        dm += kv * mu[h * DD + d];
        dp += kv * phi[h * DD + d];
        nn += kv * kv;
    }
    float halfn = 0.5f * SCALEF * nn;
    sb[j] = SCALEF * dm - halfn;
    sg[j] = SCALEF * dp - halfn;
    __syncthreads();
    float mb = -1e30f, mg = -1e30f;
    for (int t = 0; t < CHUNKK; t++) { mb = fmaxf(mb, sb[t]); mg = fmaxf(mg, sg[t]); }
    float eb = expf(sb[j] - mb), eg = expf(sg[j] - mg);
    __syncthreads();
    sb[j] = eb; sg[j] = eg;
    __syncthreads();
    float zb = 0.f, zg = 0.f;
    for (int t = 0; t < CHUNKK; t++) { zb += sb[t]; zg += sg[t]; }
    float invb = 1.f / zb, invg = 1.f / zg;
    if (j < DD) {
        int d = j;
        float acc = 0.f;
        for (int t = 0; t < CHUNKK; t++) acc += sb[t] * __half2float(kbase[(size_t)t * HIDD + d]);
        rk[((size_t)bh * NCC + c) * DD + d] = __float2half(acc * invb);
    } else {
        int d = j - DD;
        float acc = 0.f;
        for (int t = 0; t < CHUNKK; t++) acc += sg[t] * __half2float(vbase[(size_t)t * HIDD + d]);
        rv[((size_t)bh * NCC + c) * DD + d] = __float2half(acc * invg);
    }
}

// ================= MMA flash attention (fp16 ops, cp.async double-buffered K/V) =================
// smem: Q[128][144B] | buf0{K[64][144],V[64][144]} | buf1{...}
#define AQ_S   0
#define ABUF(i) (18432 + (i) * 18432)
#define AVOFF  9216
#define AT_SMEM 55296

__global__ void __launch_bounds__(128, 3)
attn_mma(const __half* __restrict__ q, const __half* __restrict__ k,
         const __half* __restrict__ v, const __half* __restrict__ rk,
         const __half* __restrict__ rv, __half* __restrict__ oh) {
    extern __shared__ char dsm[];
    const uint32_t sb = smem_u32(dsm);

    const int qt  = blockIdx.x;
    const int w   = blockIdx.y;
    const int bh  = blockIdx.z;
    const int b   = bh >> 4, h = bh & 15;
    const int tid = threadIdx.x, lane = tid & 31, wq = tid >> 5;

    const int rowoff = ((lane >> 3) & 1) * 8 + (lane & 7);
    const int koff   = (lane >> 4) * 8;
    const int vrow   = lane & 15;
    const int vnadd  = (lane >> 4) * 8;

    const __half* qg   = q + (((size_t)b * SS + w * WINN + qt * 128) * NHH + h) * DD;
    const __half* kwin = k + (((size_t)b * SS + w * WINN) * NHH + h) * DD;
    const __half* vwin = v + (((size_t)b * SS + w * WINN) * NHH + h) * DD;
    const __half* rkb  = rk + (size_t)bh * NCC * DD;
    const __half* rvb  = rv + (size_t)bh * NCC * DD;

    const int nwt    = 2 * qt + 2;
    const int nch    = 4 * w;
    const int ntile  = nwt + (nch > 0 ? 1 : 0);

    const int qrow = tid >> 3, qc8 = tid & 7;

    // ---- issue Q (group 0) ----
#pragma unroll
    for (int i = 0; i < 8; i++) {
        int r = qrow + i * 16;
        CPASYNC16(sb + AQ_S + (uint32_t)r * 144 + qc8 * 16,
                  qg + (size_t)r * HIDD + qc8 * 8);
    }
    CPCOMMIT();

    auto issue_tile = [&](int t) {
        const uint32_t kd = sb + ABUF(t & 1);
        const uint32_t vd = kd + AVOFF;
        if (t < nwt) {
            const __half* ks = kwin + (size_t)(t * 64) * HIDD;
            const __half* vs = vwin + (size_t)(t * 64) * HIDD;
#pragma unroll
            for (int i = 0; i < 4; i++) {
                int ch = tid + i * 128, r = ch >> 3, c8 = ch & 7;
                CPASYNC16(kd + (uint32_t)r * 144 + c8 * 16, ks + (size_t)r * HIDD + c8 * 8);
                CPASYNC16(vd + (uint32_t)r * 144 + c8 * 16, vs + (size_t)r * HIDD + c8 * 8);
            }
        } else {
#pragma unroll
            for (int i = 0; i < 4; i++) {
                int ch = tid + i * 128, r = ch >> 3, c8 = ch & 7;
                uint32_t sz = (r < nch) ? 16u : 0u;
                size_t off = (r < nch) ? ((size_t)r * DD + c8 * 8) : 0;
                CPASYNC16P(kd + (uint32_t)r * 144 + c8 * 16, rkb + off, sz);
                CPASYNC16P(vd + (uint32_t)r * 144 + c8 * 16, rvb + off, sz);
            }
        }
        CPCOMMIT();
    };

    issue_tile(0);
    CPWAIT1();          // Q complete (tile 0 may be in flight)
    __syncthreads();

    // pre-load Q fragments once
    uint32_t qf[4][2][4];
#pragma unroll
    for (int ks = 0; ks < 4; ks++)
#pragma unroll
        for (int mf = 0; mf < 2; mf++)
            LDSM_X4(qf[ks][mf], sb + AQ_S + (uint32_t)(wq * 32 + mf * 16 + rowoff) * 144 + (ks * 16 + koff) * 2);

    float OA[2][8][4];
#pragma unroll
    for (int mf = 0; mf < 2; mf++)
#pragma unroll
        for (int nf = 0; nf < 8; nf++)
#pragma unroll
            for (int r = 0; r < 4; r++) OA[mf][nf][r] = 0.f;
    float mrow[2][2] = {{-1e30f, -1e30f}, {-1e30f, -1e30f}};
    float lrow[2][2] = {{0.f, 0.f}, {0.f, 0.f}};

    for (int t = 0; t < ntile; t++) {
        const bool ischunk = (t == nwt);
        const int kt0 = t * 64;
        const bool more = (t + 1 < ntile);
        if (more) issue_tile(t + 1);
        if (more) { CPWAIT1(); } else { CPWAIT0(); }
        __syncthreads();

        const uint32_t kbs = sb + ABUF(t & 1);
        const uint32_t vbs = kbs + AVOFF;

        float SA[2][8][4];
#pragma unroll
        for (int mf = 0; mf < 2; mf++)
#pragma unroll
            for (int nf = 0; nf < 8; nf++)
#pragma unroll
                for (int r = 0; r < 4; r++) SA[mf][nf][r] = 0.f;

        // ---- S = Q * K^T ----
#pragma unroll
        for (int ks = 0; ks < 4; ks++) {
            uint32_t bf[4][4];
#pragma unroll
            for (int nb = 0; nb < 4; nb++)
                LDSM_X4(bf[nb], kbs + (uint32_t)(nb * 16 + rowoff) * 144 + (ks * 16 + koff) * 2);
#pragma unroll
            for (int mf = 0; mf < 2; mf++)
#pragma unroll
                for (int nf = 0; nf < 8; nf++)
                    MMAH16816(SA[mf][nf], qf[ks][mf], bf[nf >> 1][nf & 1], bf[nf >> 1][(nf & 1) + 2]);
        }

        if (ischunk) {
#pragma unroll
            for (int mf = 0; mf < 2; mf++)
#pragma unroll
                for (int nf = 0; nf < 8; nf++) {
                    int colb = nf * 8 + (lane & 3) * 2;
                    if (colb     >= nch) { SA[mf][nf][0] = -1e30f; SA[mf][nf][2] = -1e30f; }
                    if (colb + 1 >= nch) { SA[mf][nf][1] = -1e30f; SA[mf][nf][3] = -1e30f; }
                }
        } else if (t >= 2 * qt) {
#pragma unroll
            for (int mf = 0; mf < 2; mf++)
#pragma unroll
                for (int nf = 0; nf < 8; nf++) {
                    int colb = kt0 + nf * 8 + (lane & 3) * 2;
#pragma unroll
                    for (int hf = 0; hf < 2; hf++) {
                        int rowq = qt * 128 + wq * 32 + mf * 16 + (lane >> 2) + hf * 8;
                        if (colb     > rowq) SA[mf][nf][hf * 2]     = -1e30f;
                        if (colb + 1 > rowq) SA[mf][nf][hf * 2 + 1] = -1e30f;
                    }
                }
        }

#pragma unroll
        for (int mf = 0; mf < 2; mf++)
#pragma unroll
            for (int hf = 0; hf < 2; hf++) {
                float tm = -1e30f;
#pragma unroll
                for (int nf = 0; nf < 8; nf++) {
                    tm = fmaxf(tm, SA[mf][nf][hf * 2]);
                    tm = fmaxf(tm, SA[mf][nf][hf * 2 + 1]);
                }
                tm = fmaxf(tm, __shfl_xor_sync(0xFFFFFFFF, tm, 1));
                tm = fmaxf(tm, __shfl_xor_sync(0xFFFFFFFF, tm, 2));
                float mold = mrow[mf][hf];
                float mnew = fmaxf(mold, tm);
                float f = __expf(mold - mnew);
                float rs = 0.f;
#pragma unroll
                for (int nf = 0; nf < 8; nf++) {
                    float p0 = __expf(SA[mf][nf][hf * 2]     - mnew);
                    float p1 = __expf(SA[mf][nf][hf * 2 + 1] - mnew);
                    SA[mf][nf][hf * 2]     = p0;
                    SA[mf][nf][hf * 2 + 1] = p1;
                    rs += p0 + p1;
                }
                rs += __shfl_xor_sync(0xFFFFFFFF, rs, 1);
                rs += __shfl_xor_sync(0xFFFFFFFF, rs, 2);
                lrow[mf][hf] = lrow[mf][hf] * f + rs;
                mrow[mf][hf] = mnew;
#pragma unroll
                for (int nf = 0; nf < 8; nf++) {
                    OA[mf][nf][hf * 2]     *= f;
                    OA[mf][nf][hf * 2 + 1] *= f;
                }
            }

        // ---- O += P * V ----
#pragma unroll
        for (int kc = 0; kc < 4; kc++) {
            uint32_t ah[2][4];
#pragma unroll
            for (int mf = 0; mf < 2; mf++) {
                ah[mf][0] = packh2(SA[mf][2 * kc][0],     SA[mf][2 * kc][1]);
                ah[mf][1] = packh2(SA[mf][2 * kc][2],     SA[mf][2 * kc][3]);
                ah[mf][2] = packh2(SA[mf][2 * kc + 1][0], SA[mf][2 * kc + 1][1]);
                ah[mf][3] = packh2(SA[mf][2 * kc + 1][2], SA[mf][2 * kc + 1][3]);
            }
#pragma unroll
            for (int nq = 0; nq < 4; nq++) {
                uint32_t off = (uint32_t)(kc * 16 + vrow) * 144 + (nq * 16 + vnadd) * 2;
                uint32_t bv[4];
                LDSM_X4T(bv, vbs + off);
#pragma unroll
                for (int mf = 0; mf < 2; mf++) {
                    MMAH16816R(OA[mf][2 * nq],     ah[mf][0], ah[mf][1], ah[mf][2], ah[mf][3], bv[0], bv[1]);
                    MMAH16816R(OA[mf][2 * nq + 1], ah[mf][0], ah[mf][1], ah[mf][2], ah[mf][3], bv[2], bv[3]);
                }
            }
        }
        if (more) __syncthreads();
    }

    // ---- epilogue: single fp16 for O-projection ----
#pragma unroll
    for (int mf = 0; mf < 2; mf++)
#pragma unroll
        for (int hf = 0; hf < 2; hf++) {
            float inv = 1.f / lrow[mf][hf];
            int row = w * WINN + qt * 128 + wq * 32 + mf * 16 + (lane >> 2) + hf * 8;
            size_t base = ((size_t)b * SS + row) * HIDD + h * DD;
#pragma unroll
            for (int nf = 0; nf < 8; nf++) {
                int d = nf * 8 + (lane & 3) * 2;
                *(uint32_t*)(oh + base + d) = packh2(OA[mf][nf][hf * 2] * inv, OA[mf][nf][hf * 2 + 1] * inv);
            }
        }
}

// ---------------- launch ----------------
extern "C" void kernel_launch(void* const* d_in, const int* in_sizes, int n_in,
                              void* d_out, int out_size) {
    const float* hidden = (const float*)d_in[0];
    const float* Wq     = (const float*)d_in[1];
    const float* Wk     = (const float*)d_in[2];
    const float* Wv     = (const float*)d_in[3];
    const float* Wo     = (const float*)d_in[4];
    const float* mu     = (const float*)d_in[5];
    const float* phi    = (const float*)d_in[6];
    const float* cosT   = (const float*)d_in[7];
    const float* sinT   = (const float*)d_in[8];

    __half *qb, *kb, *vb, *rkb, *rvb, *hidh, *aoh, *w16;
    cudaGetSymbolAddress((void**)&qb,   g_q16);
    cudaGetSymbolAddress((void**)&kb,   g_k16);
    cudaGetSymbolAddress((void**)&vb,   g_v16);
    cudaGetSymbolAddress((void**)&rkb,  g_rfak16);
    cudaGetSymbolAddress((void**)&rvb,  g_rfav16);
    cudaGetSymbolAddress((void**)&hidh, g_hid_h);
    cudaGetSymbolAddress((void**)&aoh,  g_ao_h);
    cudaGetSymbolAddress((void**)&w16,  g_w16);

    static bool attr_set = false;
    if (!attr_set) {
        cudaFuncSetAttribute((const void*)gemm_f16,
                             cudaFuncAttributeMaxDynamicSharedMemorySize, QSMEM);
        cudaFuncSetAttribute((const void*)attn_mma,
                             cudaFuncAttributeMaxDynamicSharedMemorySize, AT_SMEM);
        attr_set = true;
    }

    const int WSZ = HIDD * HIDD;
    const int HN4 = MTOK * HIDD / 4;
    const int WN4 = WSZ / 4;

    // launches 0-1: converts; launch 2: big QKV GEMM
    cvt16_all<<<dim3((WN4 + 255) / 256, 4), 256>>>(Wq, Wk, Wv, Wo, w16, WN4);
    cvt16_one<<<(HN4 + 255) / 256, 256>>>(hidden, hidh, HN4);

    // fused QKV GEMM with RoPE, fp16 outputs (q pre-scaled by SCALEF)
    gemm_f16<<<dim3(3072 / 256, MTOK / 128), 512, QSMEM>>>(hidh, w16, qb, kb, vb, nullptr,
                                                           cosT, sinT, 1, 1);

    rfa_kernel<<<BB * NHH * NCC, 128>>>(kb, vb, mu, phi, rkb, rvb);

    attn_mma<<<dim3(4, NWW, BB * NHH), 128, AT_SMEM>>>(qb, kb, vb, rkb, rvb, aoh);

    // O projection (fp32 out to d_out)
    gemm_f16<<<dim3(1024 / 256, MTOK / 128), 512, QSMEM>>>(aoh, w16 + 3 * WSZ,
                                                           nullptr, nullptr, nullptr, (float*)d_out,
                                                           cosT, sinT, 0, 0);
}